// round 2
// baseline (speedup 1.0000x reference)
#include <cuda_runtime.h>
#include <math.h>

#define T_STEPS 512
#define BATCH   64
#define DH      1024
#define DIN     1024

// Scratch: precomputed input projections (ctilde, ix, fx), each [T,B,H] f32.
__device__ float g_ct[(size_t)T_STEPS * BATCH * DH];
__device__ float g_ix[(size_t)T_STEPS * BATCH * DH];
__device__ float g_fx[(size_t)T_STEPS * BATCH * DH];
__device__ unsigned g_bar;

// ---------------------------------------------------------------------------
// Kernel 1: fused input projections.
//   g_ct = x @ w_cx^T + b_cx ; g_ix = x @ w_ix^T + b_ix ; g_fx = x @ w_fx^T + b_fx
// Block tile: 64 rows (of T*B) x 64 cols (of H), all 3 weight matrices at once
// (x tile loaded once, used 3x). 256 threads, 4x4 register tile per matrix.
// ---------------------------------------------------------------------------
__global__ void __launch_bounds__(256) proj_kernel(
    const float* __restrict__ x,
    const float* __restrict__ w_cx, const float* __restrict__ w_ix,
    const float* __restrict__ w_fx,
    const float* __restrict__ b_cx, const float* __restrict__ b_ix,
    const float* __restrict__ b_fx)
{
    __shared__ float As[16][64];      // [k][row]
    __shared__ float Ws[3][16][64];   // [m][k][col]

    const int tid = threadIdx.x;
    const int tx  = tid & 15;         // col group
    const int ty  = tid >> 4;         // row group
    const int rowBase = blockIdx.y * 64;
    const int colBase = blockIdx.x * 64;

    // load mapping: each thread loads one float4 of x and one per weight matrix
    const int lrow = tid >> 2;        // 0..63
    const int lk   = (tid & 3) * 4;   // 0,4,8,12

    const float* xp  = x    + (size_t)(rowBase + lrow) * DIN + lk;
    const float* wp0 = w_cx + (size_t)(colBase + lrow) * DIN + lk;
    const float* wp1 = w_ix + (size_t)(colBase + lrow) * DIN + lk;
    const float* wp2 = w_fx + (size_t)(colBase + lrow) * DIN + lk;

    float acc[3][4][4];
#pragma unroll
    for (int m = 0; m < 3; m++)
#pragma unroll
        for (int i = 0; i < 4; i++)
#pragma unroll
            for (int jj = 0; jj < 4; jj++) acc[m][i][jj] = 0.f;

    // prefetch first k-tile
    float4 ga = *(const float4*)(xp);
    float4 g0 = *(const float4*)(wp0);
    float4 g1 = *(const float4*)(wp1);
    float4 g2 = *(const float4*)(wp2);

    for (int kk = 0; kk < DIN; kk += 16) {
        __syncthreads();
        As[lk + 0][lrow] = ga.x; As[lk + 1][lrow] = ga.y;
        As[lk + 2][lrow] = ga.z; As[lk + 3][lrow] = ga.w;
        Ws[0][lk + 0][lrow] = g0.x; Ws[0][lk + 1][lrow] = g0.y;
        Ws[0][lk + 2][lrow] = g0.z; Ws[0][lk + 3][lrow] = g0.w;
        Ws[1][lk + 0][lrow] = g1.x; Ws[1][lk + 1][lrow] = g1.y;
        Ws[1][lk + 2][lrow] = g1.z; Ws[1][lk + 3][lrow] = g1.w;
        Ws[2][lk + 0][lrow] = g2.x; Ws[2][lk + 1][lrow] = g2.y;
        Ws[2][lk + 2][lrow] = g2.z; Ws[2][lk + 3][lrow] = g2.w;
        __syncthreads();

        if (kk + 16 < DIN) {   // prefetch next tile (overlaps with compute)
            ga = *(const float4*)(xp  + kk + 16);
            g0 = *(const float4*)(wp0 + kk + 16);
            g1 = *(const float4*)(wp1 + kk + 16);
            g2 = *(const float4*)(wp2 + kk + 16);
        }

#pragma unroll
        for (int k = 0; k < 16; k++) {
            const float4 a4 = *(const float4*)&As[k][ty * 4];
            const float4 b0 = *(const float4*)&Ws[0][k][tx * 4];
            const float4 b1 = *(const float4*)&Ws[1][k][tx * 4];
            const float4 b2 = *(const float4*)&Ws[2][k][tx * 4];
            const float av[4] = {a4.x, a4.y, a4.z, a4.w};
            const float bv[3][4] = {{b0.x, b0.y, b0.z, b0.w},
                                    {b1.x, b1.y, b1.z, b1.w},
                                    {b2.x, b2.y, b2.z, b2.w}};
#pragma unroll
            for (int m = 0; m < 3; m++)
#pragma unroll
                for (int i = 0; i < 4; i++)
#pragma unroll
                    for (int jj = 0; jj < 4; jj++)
                        acc[m][i][jj] += av[i] * bv[m][jj];
        }
    }

    // epilogue: add biases, write float4
    const float4 bb0 = *(const float4*)(b_cx + colBase + tx * 4);
    const float4 bb1 = *(const float4*)(b_ix + colBase + tx * 4);
    const float4 bb2 = *(const float4*)(b_fx + colBase + tx * 4);
#pragma unroll
    for (int i = 0; i < 4; i++) {
        const size_t off = (size_t)(rowBase + ty * 4 + i) * DH + colBase + tx * 4;
        float4 o;
        o.x = acc[0][i][0] + bb0.x; o.y = acc[0][i][1] + bb0.y;
        o.z = acc[0][i][2] + bb0.z; o.w = acc[0][i][3] + bb0.w;
        *(float4*)(g_ct + off) = o;
        o.x = acc[1][i][0] + bb1.x; o.y = acc[1][i][1] + bb1.y;
        o.z = acc[1][i][2] + bb1.z; o.w = acc[1][i][3] + bb1.w;
        *(float4*)(g_ix + off) = o;
        o.x = acc[2][i][0] + bb2.x; o.y = acc[2][i][1] + bb2.y;
        o.z = acc[2][i][2] + bb2.z; o.w = acc[2][i][3] + bb2.w;
        *(float4*)(g_fx + off) = o;
    }
}

// ---------------------------------------------------------------------------
// Kernel 2: persistent recurrence. 128 blocks x 256 threads, software grid
// barrier per timestep. Block j owns h-columns [j*8, j*8+8); both gate weight
// slices (w_ic, w_fc rows) live in shared memory for all 512 steps.
// Warp w handles column j*8+w; lane handles rows (2*lane, 2*lane+1).
// ---------------------------------------------------------------------------
#define RBLOCKS 128
#define RSMEM   ((16 * 1024 + 32 * 64) * 4)   // 64KB weights + 8KB h tile

__global__ void __launch_bounds__(256) recur_kernel(
    const float* __restrict__ h0,
    const float* __restrict__ w_ic, const float* __restrict__ w_fc,
    const float* __restrict__ b_ic, const float* __restrict__ b_fc,
    float* __restrict__ out)
{
    extern __shared__ float sm[];
    float* wi_s = sm;               // [8][1024]
    float* wf_s = sm + 8 * DH;      // [8][1024]
    float* hs   = sm + 16 * DH;     // [32][64]  ([k][row])

    const int tid  = threadIdx.x;
    const int w    = tid >> 5;          // warp id = local column
    const int lane = tid & 31;
    const int jb   = blockIdx.x;
    const int col  = jb * 8 + w;
    const int r0   = lane * 2;

    // preload this block's weight slices (8 rows x 1024 each, both gates)
    {
        const float4* gi = (const float4*)(w_ic + (size_t)jb * 8 * DH);
        const float4* gf = (const float4*)(w_fc + (size_t)jb * 8 * DH);
        float4* si = (float4*)wi_s;
        float4* sf = (float4*)wf_s;
        for (int i = tid; i < 8 * DH / 4; i += 256) { si[i] = gi[i]; sf[i] = gf[i]; }
    }
    const float bi = b_ic[col];
    const float bf = b_fc[col];
    const float* wi_row = wi_s + w * DH;
    const float* wf_row = wf_s + w * DH;
    __syncthreads();

    const int frow = tid & 63;          // fill mapping: row
    const int fkq  = tid >> 6;          // fill mapping: k-quad (0..3, +4 for 2nd)
    const unsigned nb = gridDim.x;

    const float* hprev = h0;
    for (int t = 0; t < T_STEPS; t++) {
        float ai0 = 0.f, ai1 = 0.f, af0 = 0.f, af1 = 0.f;

        float4 p0 = *(const float4*)(hprev + (size_t)frow * DH + fkq * 4);
        float4 p1 = *(const float4*)(hprev + (size_t)frow * DH + (fkq + 4) * 4);

        for (int kk = 0; kk < DH; kk += 32) {
            __syncthreads();
            hs[(fkq * 4 + 0) * 64 + frow] = p0.x;
            hs[(fkq * 4 + 1) * 64 + frow] = p0.y;
            hs[(fkq * 4 + 2) * 64 + frow] = p0.z;
            hs[(fkq * 4 + 3) * 64 + frow] = p0.w;
            hs[((fkq + 4) * 4 + 0) * 64 + frow] = p1.x;
            hs[((fkq + 4) * 4 + 1) * 64 + frow] = p1.y;
            hs[((fkq + 4) * 4 + 2) * 64 + frow] = p1.z;
            hs[((fkq + 4) * 4 + 3) * 64 + frow] = p1.w;
            __syncthreads();

            if (kk + 32 < DH) {   // prefetch next h tile
                p0 = *(const float4*)(hprev + (size_t)frow * DH + kk + 32 + fkq * 4);
                p1 = *(const float4*)(hprev + (size_t)frow * DH + kk + 32 + (fkq + 4) * 4);
            }

#pragma unroll
            for (int k = 0; k < 32; k += 4) {
                const float4 wi4 = *(const float4*)(wi_row + kk + k);
                const float4 wf4 = *(const float4*)(wf_row + kk + k);
                float2 h;
                h = *(const float2*)(hs + (k + 0) * 64 + r0);
                ai0 += h.x * wi4.x; ai1 += h.y * wi4.x;
                af0 += h.x * wf4.x; af1 += h.y * wf4.x;
                h = *(const float2*)(hs + (k + 1) * 64 + r0);
                ai0 += h.x * wi4.y; ai1 += h.y * wi4.y;
                af0 += h.x * wf4.y; af1 += h.y * wf4.y;
                h = *(const float2*)(hs + (k + 2) * 64 + r0);
                ai0 += h.x * wi4.z; ai1 += h.y * wi4.z;
                af0 += h.x * wf4.z; af1 += h.y * wf4.z;
                h = *(const float2*)(hs + (k + 3) * 64 + r0);
                ai0 += h.x * wi4.w; ai1 += h.y * wi4.w;
                af0 += h.x * wf4.w; af1 += h.y * wf4.w;
            }
        }

        // gates + cell update + output
        const size_t ob = (size_t)t * (BATCH * DH);
        const size_t i0 = ob + (size_t)r0 * DH + col;
        const size_t i1 = i0 + DH;

        const float pi0 = ai0 + bi + g_ix[i0];
        const float pf0 = af0 + bf + g_fx[i0];
        const float pi1 = ai1 + bi + g_ix[i1];
        const float pf1 = af1 + bf + g_fx[i1];
        const float ig0 = 1.f / (1.f + expf(-pi0));
        const float fg0 = 1.f / (1.f + expf(-pf0));
        const float ig1 = 1.f / (1.f + expf(-pi1));
        const float fg1 = 1.f / (1.f + expf(-pf1));
        const float hp0 = hprev[(size_t)r0 * DH + col];
        const float hp1 = hprev[(size_t)(r0 + 1) * DH + col];
        const float c0 = ig0 * g_ct[i0] + fg0 * hp0;
        const float c1 = ig1 * g_ct[i1] + fg1 * hp1;
        const float hn0 = tanhf(c0);
        const float hn1 = tanhf(c1);
        out[i0] = hn0;
        out[i1] = hn1;
        if (t == T_STEPS - 1) {   // h_last tail of d_out
            const size_t tb = (size_t)T_STEPS * BATCH * DH;
            out[tb + (size_t)r0 * DH + col]       = hn0;
            out[tb + (size_t)(r0 + 1) * DH + col] = hn1;
        }

        // grid-wide barrier (monotonic counter; reset host-side each launch)
        __threadfence();
        __syncthreads();
        if (tid == 0) {
            atomicAdd(&g_bar, 1u);
            const unsigned target = (unsigned)(t + 1) * nb;
            while (*((volatile unsigned*)&g_bar) < target) { }
            __threadfence();
        }
        __syncthreads();

        hprev = out + ob;
    }
}

// ---------------------------------------------------------------------------
extern "C" void kernel_launch(void* const* d_in, const int* in_sizes, int n_in,
                              void* d_out, int out_size)
{
    const float* x    = (const float*)d_in[0];
    const float* h0   = (const float*)d_in[1];
    const float* w_cx = (const float*)d_in[2];
    const float* w_ic = (const float*)d_in[3];
    const float* w_ix = (const float*)d_in[4];
    const float* w_fc = (const float*)d_in[5];
    const float* w_fx = (const float*)d_in[6];
    const float* b_cx = (const float*)d_in[7];
    const float* b_ic = (const float*)d_in[8];
    const float* b_ix = (const float*)d_in[9];
    const float* b_fc = (const float*)d_in[10];
    const float* b_fx = (const float*)d_in[11];
    float* out = (float*)d_out;

    // reset grid-barrier counter (graph-capturable async memset)
    void* barAddr = nullptr;
    cudaGetSymbolAddress(&barAddr, g_bar);
    cudaMemsetAsync(barAddr, 0, sizeof(unsigned), 0);

    // 1) input projections
    dim3 pgrid(DH / 64, (T_STEPS * BATCH) / 64);   // (16, 512)
    proj_kernel<<<pgrid, 256>>>(x, w_cx, w_ix, w_fx, b_cx, b_ix, b_fx);

    // 2) persistent recurrence
    cudaFuncSetAttribute(recur_kernel,
                         cudaFuncAttributeMaxDynamicSharedMemorySize, RSMEM);
    recur_kernel<<<RBLOCKS, 256, RSMEM>>>(h0, w_ic, w_fc, b_ic, b_fc, out);
}

// round 3
// speedup vs baseline: 1.2357x; 1.2357x over previous
#include <cuda_runtime.h>
#include <math.h>

#define T_STEPS 512
#define BATCH   64
#define DH      1024
#define DIN     1024

// Scratch: precomputed input projections (ctilde, ix, fx), each [T,B,H] f32.
__device__ float g_ct[(size_t)T_STEPS * BATCH * DH];
__device__ float g_ix[(size_t)T_STEPS * BATCH * DH];
__device__ float g_fx[(size_t)T_STEPS * BATCH * DH];
__device__ unsigned g_bar;

// ---------------------------------------------------------------------------
// Kernel 1: fused input projections (unchanged from R1 — passed, ~FMA bound).
// ---------------------------------------------------------------------------
__global__ void __launch_bounds__(256) proj_kernel(
    const float* __restrict__ x,
    const float* __restrict__ w_cx, const float* __restrict__ w_ix,
    const float* __restrict__ w_fx,
    const float* __restrict__ b_cx, const float* __restrict__ b_ix,
    const float* __restrict__ b_fx)
{
    __shared__ float As[16][64];      // [k][row]
    __shared__ float Ws[3][16][64];   // [m][k][col]

    const int tid = threadIdx.x;
    const int tx  = tid & 15;
    const int ty  = tid >> 4;
    const int rowBase = blockIdx.y * 64;
    const int colBase = blockIdx.x * 64;

    const int lrow = tid >> 2;
    const int lk   = (tid & 3) * 4;

    const float* xp  = x    + (size_t)(rowBase + lrow) * DIN + lk;
    const float* wp0 = w_cx + (size_t)(colBase + lrow) * DIN + lk;
    const float* wp1 = w_ix + (size_t)(colBase + lrow) * DIN + lk;
    const float* wp2 = w_fx + (size_t)(colBase + lrow) * DIN + lk;

    float acc[3][4][4];
#pragma unroll
    for (int m = 0; m < 3; m++)
#pragma unroll
        for (int i = 0; i < 4; i++)
#pragma unroll
            for (int jj = 0; jj < 4; jj++) acc[m][i][jj] = 0.f;

    float4 ga = *(const float4*)(xp);
    float4 g0 = *(const float4*)(wp0);
    float4 g1 = *(const float4*)(wp1);
    float4 g2 = *(const float4*)(wp2);

    for (int kk = 0; kk < DIN; kk += 16) {
        __syncthreads();
        As[lk + 0][lrow] = ga.x; As[lk + 1][lrow] = ga.y;
        As[lk + 2][lrow] = ga.z; As[lk + 3][lrow] = ga.w;
        Ws[0][lk + 0][lrow] = g0.x; Ws[0][lk + 1][lrow] = g0.y;
        Ws[0][lk + 2][lrow] = g0.z; Ws[0][lk + 3][lrow] = g0.w;
        Ws[1][lk + 0][lrow] = g1.x; Ws[1][lk + 1][lrow] = g1.y;
        Ws[1][lk + 2][lrow] = g1.z; Ws[1][lk + 3][lrow] = g1.w;
        Ws[2][lk + 0][lrow] = g2.x; Ws[2][lk + 1][lrow] = g2.y;
        Ws[2][lk + 2][lrow] = g2.z; Ws[2][lk + 3][lrow] = g2.w;
        __syncthreads();

        if (kk + 16 < DIN) {
            ga = *(const float4*)(xp  + kk + 16);
            g0 = *(const float4*)(wp0 + kk + 16);
            g1 = *(const float4*)(wp1 + kk + 16);
            g2 = *(const float4*)(wp2 + kk + 16);
        }

#pragma unroll
        for (int k = 0; k < 16; k++) {
            const float4 a4 = *(const float4*)&As[k][ty * 4];
            const float4 b0 = *(const float4*)&Ws[0][k][tx * 4];
            const float4 b1 = *(const float4*)&Ws[1][k][tx * 4];
            const float4 b2 = *(const float4*)&Ws[2][k][tx * 4];
            const float av[4] = {a4.x, a4.y, a4.z, a4.w};
            const float bv[3][4] = {{b0.x, b0.y, b0.z, b0.w},
                                    {b1.x, b1.y, b1.z, b1.w},
                                    {b2.x, b2.y, b2.z, b2.w}};
#pragma unroll
            for (int m = 0; m < 3; m++)
#pragma unroll
                for (int i = 0; i < 4; i++)
#pragma unroll
                    for (int jj = 0; jj < 4; jj++)
                        acc[m][i][jj] += av[i] * bv[m][jj];
        }
    }

    const float4 bb0 = *(const float4*)(b_cx + colBase + tx * 4);
    const float4 bb1 = *(const float4*)(b_ix + colBase + tx * 4);
    const float4 bb2 = *(const float4*)(b_fx + colBase + tx * 4);
#pragma unroll
    for (int i = 0; i < 4; i++) {
        const size_t off = (size_t)(rowBase + ty * 4 + i) * DH + colBase + tx * 4;
        float4 o;
        o.x = acc[0][i][0] + bb0.x; o.y = acc[0][i][1] + bb0.y;
        o.z = acc[0][i][2] + bb0.z; o.w = acc[0][i][3] + bb0.w;
        *(float4*)(g_ct + off) = o;
        o.x = acc[1][i][0] + bb1.x; o.y = acc[1][i][1] + bb1.y;
        o.z = acc[1][i][2] + bb1.z; o.w = acc[1][i][3] + bb1.w;
        *(float4*)(g_ix + off) = o;
        o.x = acc[2][i][0] + bb2.x; o.y = acc[2][i][1] + bb2.y;
        o.z = acc[2][i][2] + bb2.z; o.w = acc[2][i][3] + bb2.w;
        *(float4*)(g_fx + off) = o;
    }
}

// ---------------------------------------------------------------------------
// Kernel 2: persistent recurrence, restructured for smem-traffic reuse.
//
// 128 blocks x 256 threads. Block jb owns 8 h-columns. Thread decomposition:
//   kc = tid>>6 (k-chunk of 256), cg = (tid>>4)&3 (pair of cols), rg = tid&15.
// Thread computes 2 cols x 4 rows (rg, rg+16, rg+32, rg+48) x 2 gates over
// its 256-wide k chunk -> 16 fp32 accumulators; 4-way kc reduction via smem.
// Weights (2x8x1024) resident in smem for all 512 steps; h staged per step in
// a padded [64 rows][65] tile, 16 k per kc per stage, conflict-free reads.
// Per-SM per-step: FMA 16.4K cyc (floor), LDS ~13K cyc -> FMA bound.
// ---------------------------------------------------------------------------
#define RBLOCKS   128
#define HS_STRIDE 65
#define HS_SIZE   (64 * HS_STRIDE)                 // 4160 floats
#define RSMEM     ((16 * DH + HS_SIZE) * 4)        // ~82 KB

__global__ void __launch_bounds__(256) recur_kernel(
    const float* __restrict__ h0,
    const float* __restrict__ w_ic, const float* __restrict__ w_fc,
    const float* __restrict__ b_ic, const float* __restrict__ b_fc,
    float* __restrict__ out)
{
    extern __shared__ float sm[];
    float* wi_s = sm;                // [8][1024]
    float* wf_s = sm + 8 * DH;       // [8][1024]
    float* hs   = sm + 16 * DH;      // [64][65] h tile; reused as reduction buf

    const int tid = threadIdx.x;
    const int kc  = tid >> 6;        // 0..3  k-chunk
    const int cg  = (tid >> 4) & 3;  // 0..3  col pair
    const int rg  = tid & 15;        // 0..15 row group
    const int jb  = blockIdx.x;
    const int c0  = cg * 2;          // local col base
    const int colg = jb * 8 + c0;    // global col base

    // preload this block's weight slices (8 rows x 1024, both gates)
    {
        const float4* gi = (const float4*)(w_ic + (size_t)jb * 8 * DH);
        const float4* gf = (const float4*)(w_fc + (size_t)jb * 8 * DH);
        float4* si = (float4*)wi_s;
        float4* sf = (float4*)wf_s;
        for (int i = tid; i < 8 * DH / 4; i += 256) { si[i] = gi[i]; sf[i] = gf[i]; }
    }
    const float* wiA = wi_s + (size_t)c0 * DH;
    const float* wiB = wi_s + (size_t)(c0 + 1) * DH;
    const float* wfA = wf_s + (size_t)c0 * DH;
    const float* wfB = wf_s + (size_t)(c0 + 1) * DH;
    const float biA = b_ic[colg], biB = b_ic[colg + 1];
    const float bfA = b_fc[colg], bfB = b_fc[colg + 1];
    __syncthreads();

    const unsigned nb = gridDim.x;
    const float* hprev = h0;

    // h-read base for the compute loop: hs[row*65 + kc*16 + kloc]
    const float* hbase = hs + kc * 16 + rg * HS_STRIDE;

    for (int t = 0; t < T_STEPS; t++) {
        float accI[2][4], accF[2][4];
#pragma unroll
        for (int c = 0; c < 2; c++)
#pragma unroll
            for (int m = 0; m < 4; m++) { accI[c][m] = 0.f; accF[c][m] = 0.f; }

        // prefetch stage 0 (post-barrier: hprev is stable)
        float4 pf[4];
#pragma unroll
        for (int u = 0; u < 4; u++) {
            const int fi = tid + 256 * u;
            const int frow = fi >> 4, fq = fi & 15;
            const int fkc = fq >> 2, fj = fq & 3;
            pf[u] = *(const float4*)(hprev + (size_t)frow * DH + fkc * 256 + fj * 4);
        }

        for (int s = 0; s < 16; s++) {
            __syncthreads();   // previous stage's compute done
#pragma unroll
            for (int u = 0; u < 4; u++) {
                const int fi = tid + 256 * u;
                const int frow = fi >> 4, fq = fi & 15;
                const int fkc = fq >> 2, fj = fq & 3;
                float* dst = hs + frow * HS_STRIDE + fkc * 16 + fj * 4;
                dst[0] = pf[u].x; dst[1] = pf[u].y; dst[2] = pf[u].z; dst[3] = pf[u].w;
            }
            __syncthreads();

            if (s < 15) {      // prefetch next stage, overlaps with compute
#pragma unroll
                for (int u = 0; u < 4; u++) {
                    const int fi = tid + 256 * u;
                    const int frow = fi >> 4, fq = fi & 15;
                    const int fkc = fq >> 2, fj = fq & 3;
                    pf[u] = *(const float4*)(hprev + (size_t)frow * DH
                                             + fkc * 256 + (s + 1) * 16 + fj * 4);
                }
            }

            const int kb = kc * 256 + s * 16;   // global k base of this chunk
#pragma unroll
            for (int k4 = 0; k4 < 4; k4++) {
                const float4 wi4A = *(const float4*)(wiA + kb + k4 * 4);
                const float4 wi4B = *(const float4*)(wiB + kb + k4 * 4);
                const float4 wf4A = *(const float4*)(wfA + kb + k4 * 4);
                const float4 wf4B = *(const float4*)(wfB + kb + k4 * 4);
                const float wiAv[4] = {wi4A.x, wi4A.y, wi4A.z, wi4A.w};
                const float wiBv[4] = {wi4B.x, wi4B.y, wi4B.z, wi4B.w};
                const float wfAv[4] = {wf4A.x, wf4A.y, wf4A.z, wf4A.w};
                const float wfBv[4] = {wf4B.x, wf4B.y, wf4B.z, wf4B.w};
#pragma unroll
                for (int j = 0; j < 4; j++) {
                    const int kl = k4 * 4 + j;
#pragma unroll
                    for (int m = 0; m < 4; m++) {
                        const float hv = hbase[m * 16 * HS_STRIDE + kl];
                        accI[0][m] += hv * wiAv[j];
                        accI[1][m] += hv * wiBv[j];
                        accF[0][m] += hv * wfAv[j];
                        accF[1][m] += hv * wfBv[j];
                    }
                }
            }
        }

        // ---- kc reduction through smem (stride-17 pad: conflict-free) ----
        __syncthreads();           // all compute done; hs reusable
        const int lid = cg * 16 + rg;
        if (kc > 0) {
            float* r = hs + ((kc - 1) * 64 + lid) * 17;
#pragma unroll
            for (int c = 0; c < 2; c++)
#pragma unroll
                for (int m = 0; m < 4; m++) {
                    r[c * 4 + m]     = accI[c][m];
                    r[8 + c * 4 + m] = accF[c][m];
                }
        }
        __syncthreads();

        const size_t ob = (size_t)t * (BATCH * DH);
        if (kc == 0) {
#pragma unroll
            for (int rk = 0; rk < 3; rk++) {
                const float* r = hs + (rk * 64 + lid) * 17;
#pragma unroll
                for (int c = 0; c < 2; c++)
#pragma unroll
                    for (int m = 0; m < 4; m++) {
                        accI[c][m] += r[c * 4 + m];
                        accF[c][m] += r[8 + c * 4 + m];
                    }
            }
            // gates + cell update + output: 2 cols x 4 rows
#pragma unroll
            for (int m = 0; m < 4; m++) {
                const int row = rg + 16 * m;
                const size_t base = ob + (size_t)row * DH + colg;
#pragma unroll
                for (int c = 0; c < 2; c++) {
                    const float bi = c ? biB : biA;
                    const float bf = c ? bfB : bfA;
                    const float pi = accI[c][m] + bi + g_ix[base + c];
                    const float pv = accF[c][m] + bf + g_fx[base + c];
                    const float ig = 1.f / (1.f + expf(-pi));
                    const float fg = 1.f / (1.f + expf(-pv));
                    const float hp = hprev[(size_t)row * DH + colg + c];
                    const float cc = ig * g_ct[base + c] + fg * hp;
                    const float hn = tanhf(cc);
                    out[base + c] = hn;
                    if (t == T_STEPS - 1) {
                        const size_t tb = (size_t)T_STEPS * BATCH * DH;
                        out[tb + (size_t)row * DH + colg + c] = hn;
                    }
                }
            }
        }

        // ---- grid-wide barrier (monotonic counter; host resets per launch) ----
        __threadfence();
        __syncthreads();
        if (tid == 0) {
            atomicAdd(&g_bar, 1u);
            const unsigned target = (unsigned)(t + 1) * nb;
            while (*((volatile unsigned*)&g_bar) < target) { }
            __threadfence();
        }
        __syncthreads();

        hprev = out + ob;
    }
}

// ---------------------------------------------------------------------------
extern "C" void kernel_launch(void* const* d_in, const int* in_sizes, int n_in,
                              void* d_out, int out_size)
{
    const float* x    = (const float*)d_in[0];
    const float* h0   = (const float*)d_in[1];
    const float* w_cx = (const float*)d_in[2];
    const float* w_ic = (const float*)d_in[3];
    const float* w_ix = (const float*)d_in[4];
    const float* w_fc = (const float*)d_in[5];
    const float* w_fx = (const float*)d_in[6];
    const float* b_cx = (const float*)d_in[7];
    const float* b_ic = (const float*)d_in[8];
    const float* b_ix = (const float*)d_in[9];
    const float* b_fc = (const float*)d_in[10];
    const float* b_fx = (const float*)d_in[11];
    float* out = (float*)d_out;

    // reset grid-barrier counter (graph-capturable async memset)
    void* barAddr = nullptr;
    cudaGetSymbolAddress(&barAddr, g_bar);
    cudaMemsetAsync(barAddr, 0, sizeof(unsigned), 0);

    // 1) input projections
    dim3 pgrid(DH / 64, (T_STEPS * BATCH) / 64);   // (16, 512)
    proj_kernel<<<pgrid, 256>>>(x, w_cx, w_ix, w_fx, b_cx, b_ix, b_fx);

    // 2) persistent recurrence
    cudaFuncSetAttribute(recur_kernel,
                         cudaFuncAttributeMaxDynamicSharedMemorySize, RSMEM);
    recur_kernel<<<RBLOCKS, 256, RSMEM>>>(h0, w_ic, w_fc, b_ic, b_fc, out);
}

// round 6
// speedup vs baseline: 1.3136x; 1.0630x over previous
#include <cuda_runtime.h>
#include <math.h>

#define T_STEPS 512
#define BATCH   64
#define DH      1024
#define DIN     1024

// Scratch: precomputed input projections (ctilde, ix, fx), each [T,B,H] f32.
__device__ float g_ct[(size_t)T_STEPS * BATCH * DH];
__device__ float g_ix[(size_t)T_STEPS * BATCH * DH];
__device__ float g_fx[(size_t)T_STEPS * BATCH * DH];
__device__ unsigned g_bar;

// ---------------------------------------------------------------------------
// Kernel 1: fused input projections (measured ~FMA-bound at fp32).
// ---------------------------------------------------------------------------
__global__ void __launch_bounds__(256) proj_kernel(
    const float* __restrict__ x,
    const float* __restrict__ w_cx, const float* __restrict__ w_ix,
    const float* __restrict__ w_fx,
    const float* __restrict__ b_cx, const float* __restrict__ b_ix,
    const float* __restrict__ b_fx)
{
    __shared__ float As[16][64];      // [k][row]
    __shared__ float Ws[3][16][64];   // [m][k][col]

    const int tid = threadIdx.x;
    const int tx  = tid & 15;
    const int ty  = tid >> 4;
    const int rowBase = blockIdx.y * 64;
    const int colBase = blockIdx.x * 64;

    const int lrow = tid >> 2;
    const int lk   = (tid & 3) * 4;

    const float* xp  = x    + (size_t)(rowBase + lrow) * DIN + lk;
    const float* wp0 = w_cx + (size_t)(colBase + lrow) * DIN + lk;
    const float* wp1 = w_ix + (size_t)(colBase + lrow) * DIN + lk;
    const float* wp2 = w_fx + (size_t)(colBase + lrow) * DIN + lk;

    float acc[3][4][4];
#pragma unroll
    for (int m = 0; m < 3; m++)
#pragma unroll
        for (int i = 0; i < 4; i++)
#pragma unroll
            for (int jj = 0; jj < 4; jj++) acc[m][i][jj] = 0.f;

    float4 ga = *(const float4*)(xp);
    float4 g0 = *(const float4*)(wp0);
    float4 g1 = *(const float4*)(wp1);
    float4 g2 = *(const float4*)(wp2);

    for (int kk = 0; kk < DIN; kk += 16) {
        __syncthreads();
        As[lk + 0][lrow] = ga.x; As[lk + 1][lrow] = ga.y;
        As[lk + 2][lrow] = ga.z; As[lk + 3][lrow] = ga.w;
        Ws[0][lk + 0][lrow] = g0.x; Ws[0][lk + 1][lrow] = g0.y;
        Ws[0][lk + 2][lrow] = g0.z; Ws[0][lk + 3][lrow] = g0.w;
        Ws[1][lk + 0][lrow] = g1.x; Ws[1][lk + 1][lrow] = g1.y;
        Ws[1][lk + 2][lrow] = g1.z; Ws[1][lk + 3][lrow] = g1.w;
        Ws[2][lk + 0][lrow] = g2.x; Ws[2][lk + 1][lrow] = g2.y;
        Ws[2][lk + 2][lrow] = g2.z; Ws[2][lk + 3][lrow] = g2.w;
        __syncthreads();

        if (kk + 16 < DIN) {
            ga = *(const float4*)(xp  + kk + 16);
            g0 = *(const float4*)(wp0 + kk + 16);
            g1 = *(const float4*)(wp1 + kk + 16);
            g2 = *(const float4*)(wp2 + kk + 16);
        }

#pragma unroll
        for (int k = 0; k < 16; k++) {
            const float4 a4 = *(const float4*)&As[k][ty * 4];
            const float4 b0 = *(const float4*)&Ws[0][k][tx * 4];
            const float4 b1 = *(const float4*)&Ws[1][k][tx * 4];
            const float4 b2 = *(const float4*)&Ws[2][k][tx * 4];
            const float av[4] = {a4.x, a4.y, a4.z, a4.w};
            const float bv[3][4] = {{b0.x, b0.y, b0.z, b0.w},
                                    {b1.x, b1.y, b1.z, b1.w},
                                    {b2.x, b2.y, b2.z, b2.w}};
#pragma unroll
            for (int m = 0; m < 3; m++)
#pragma unroll
                for (int i = 0; i < 4; i++)
#pragma unroll
                    for (int jj = 0; jj < 4; jj++)
                        acc[m][i][jj] += av[i] * bv[m][jj];
        }
    }

    const float4 bb0 = *(const float4*)(b_cx + colBase + tx * 4);
    const float4 bb1 = *(const float4*)(b_ix + colBase + tx * 4);
    const float4 bb2 = *(const float4*)(b_fx + colBase + tx * 4);
#pragma unroll
    for (int i = 0; i < 4; i++) {
        const size_t off = (size_t)(rowBase + ty * 4 + i) * DH + colBase + tx * 4;
        float4 o;
        o.x = acc[0][i][0] + bb0.x; o.y = acc[0][i][1] + bb0.y;
        o.z = acc[0][i][2] + bb0.z; o.w = acc[0][i][3] + bb0.w;
        *(float4*)(g_ct + off) = o;
        o.x = acc[1][i][0] + bb1.x; o.y = acc[1][i][1] + bb1.y;
        o.z = acc[1][i][2] + bb1.z; o.w = acc[1][i][3] + bb1.w;
        *(float4*)(g_ix + off) = o;
        o.x = acc[2][i][0] + bb2.x; o.y = acc[2][i][1] + bb2.y;
        o.z = acc[2][i][2] + bb2.z; o.w = acc[2][i][3] + bb2.w;
        *(float4*)(g_fx + off) = o;
    }
}

// ---------------------------------------------------------------------------
// Kernel 2: persistent recurrence, vectorized-LDS version.
//
// 128 blocks x 256 threads; block owns 8 h-columns. Thread decomposition:
//   kc = tid>>6 (256-wide k chunk), cg = (tid>>4)&3 (col pair), rg = tid&15.
// h tile double-buffered [64 rows][64 k] with row stride 68 (float4-aligned,
// conflict-free LDS.128). Inner loop: per k-quad, 4 h float4 loads + 4 weight
// float4 loads (broadcast) -> 64 FMA. Per thread per step: 512 LDS.128 vs
// 4096 FMA -> FMA pipe is the only saturated pipe (~16.4K cyc/SM/step).
// One __syncthreads per stage (double buffer), global prefetch overlapped.
// ---------------------------------------------------------------------------
#define RBLOCKS   128
#define HS_STRIDE 68
#define HS_TILE   (64 * HS_STRIDE)                     // 4352 floats / buffer
#define RSMEM     ((16 * DH + 2 * HS_TILE) * 4)        // ~98 KB

__global__ void __launch_bounds__(256) recur_kernel(
    const float* __restrict__ h0,
    const float* __restrict__ w_ic, const float* __restrict__ w_fc,
    const float* __restrict__ b_ic, const float* __restrict__ b_fc,
    float* __restrict__ out)
{
    extern __shared__ float sm[];
    float* wi_s = sm;                 // [8][1024]
    float* wf_s = sm + 8 * DH;        // [8][1024]
    float* hs0  = sm + 16 * DH;       // h tile buffer 0 (also reduction scratch)
    float* hs1  = hs0 + HS_TILE;      // h tile buffer 1

    const int tid = threadIdx.x;
    const int kc  = tid >> 6;         // 0..3
    const int cg  = (tid >> 4) & 3;   // 0..3
    const int rg  = tid & 15;         // 0..15
    const int jb  = blockIdx.x;
    const int c0  = cg * 2;
    const int colg = jb * 8 + c0;

    // preload weight slices (8 rows x 1024, both gates)
    {
        const float4* gi = (const float4*)(w_ic + (size_t)jb * 8 * DH);
        const float4* gf = (const float4*)(w_fc + (size_t)jb * 8 * DH);
        float4* si = (float4*)wi_s;
        float4* sf = (float4*)wf_s;
        for (int i = tid; i < 8 * DH / 4; i += 256) { si[i] = gi[i]; sf[i] = gf[i]; }
    }
    const float* wiA = wi_s + (size_t)c0 * DH;
    const float* wiB = wi_s + (size_t)(c0 + 1) * DH;
    const float* wfA = wf_s + (size_t)c0 * DH;
    const float* wfB = wf_s + (size_t)(c0 + 1) * DH;
    const float biA = b_ic[colg], biB = b_ic[colg + 1];
    const float bfA = b_fc[colg], bfB = b_fc[colg + 1];
    __syncthreads();

    const unsigned nb = gridDim.x;
    const float* hprev = h0;

    const int fi0   = tid;
    const int rdoff = rg * HS_STRIDE + kc * 16;

    for (int t = 0; t < T_STEPS; t++) {
        float accI[2][4], accF[2][4];
#pragma unroll
        for (int c = 0; c < 2; c++)
#pragma unroll
            for (int m = 0; m < 4; m++) { accI[c][m] = 0.f; accF[c][m] = 0.f; }

        float4 pf[4];
        // prefetch + store stage 0 (post-barrier: hprev stable)
#pragma unroll
        for (int u = 0; u < 4; u++) {
            const int fi = fi0 + 256 * u;
            const int frow = fi >> 4, fq = fi & 15;
            const int fkc = fq >> 2, fj = fq & 3;
            pf[u] = *(const float4*)(hprev + (size_t)frow * DH + fkc * 256 + fj * 4);
        }
#pragma unroll
        for (int u = 0; u < 4; u++) {
            const int fi = fi0 + 256 * u;
            const int frow = fi >> 4, fq = fi & 15;
            const int fkc = fq >> 2, fj = fq & 3;
            *(float4*)(hs0 + frow * HS_STRIDE + fkc * 16 + fj * 4) = pf[u];
        }
        __syncthreads();

#pragma unroll 1
        for (int s = 0; s < 16; s++) {
            const float* cur = (s & 1) ? hs1 : hs0;
            float* nxt = (s & 1) ? hs0 : hs1;

            if (s < 15) {   // issue next-stage global loads first (overlap)
#pragma unroll
                for (int u = 0; u < 4; u++) {
                    const int fi = fi0 + 256 * u;
                    const int frow = fi >> 4, fq = fi & 15;
                    const int fkc = fq >> 2, fj = fq & 3;
                    pf[u] = *(const float4*)(hprev + (size_t)frow * DH
                                             + fkc * 256 + (s + 1) * 16 + fj * 4);
                }
            }

            const int kb = kc * 256 + s * 16;
            const float* cb = cur + rdoff;
#pragma unroll
            for (int k4 = 0; k4 < 4; k4++) {
                const float4 h0v = *(const float4*)(cb + k4 * 4 + 0 * 16 * HS_STRIDE);
                const float4 h1v = *(const float4*)(cb + k4 * 4 + 1 * 16 * HS_STRIDE);
                const float4 h2v = *(const float4*)(cb + k4 * 4 + 2 * 16 * HS_STRIDE);
                const float4 h3v = *(const float4*)(cb + k4 * 4 + 3 * 16 * HS_STRIDE);
                const float4 wiAv = *(const float4*)(wiA + kb + k4 * 4);
                const float4 wiBv = *(const float4*)(wiB + kb + k4 * 4);
                const float4 wfAv = *(const float4*)(wfA + kb + k4 * 4);
                const float4 wfBv = *(const float4*)(wfB + kb + k4 * 4);
                const float hm[4][4] = {{h0v.x, h0v.y, h0v.z, h0v.w},
                                        {h1v.x, h1v.y, h1v.z, h1v.w},
                                        {h2v.x, h2v.y, h2v.z, h2v.w},
                                        {h3v.x, h3v.y, h3v.z, h3v.w}};
                const float wa[4] = {wiAv.x, wiAv.y, wiAv.z, wiAv.w};
                const float wb[4] = {wiBv.x, wiBv.y, wiBv.z, wiBv.w};
                const float wc[4] = {wfAv.x, wfAv.y, wfAv.z, wfAv.w};
                const float wd[4] = {wfBv.x, wfBv.y, wfBv.z, wfBv.w};
#pragma unroll
                for (int j = 0; j < 4; j++)
#pragma unroll
                    for (int m = 0; m < 4; m++) {
                        accI[0][m] += hm[m][j] * wa[j];
                        accI[1][m] += hm[m][j] * wb[j];
                        accF[0][m] += hm[m][j] * wc[j];
                        accF[1][m] += hm[m][j] * wd[j];
                    }
            }

            if (s < 15) {
#pragma unroll
                for (int u = 0; u < 4; u++) {
                    const int fi = fi0 + 256 * u;
                    const int frow = fi >> 4, fq = fi & 15;
                    const int fkc = fq >> 2, fj = fq & 3;
                    *(float4*)(nxt + frow * HS_STRIDE + fkc * 16 + fj * 4) = pf[u];
                }
                __syncthreads();
            }
        }

        // ---- kc reduction through smem (stride-17 pad; scratch = hs0) ----
        __syncthreads();           // all compute done; hs0 reusable
        const int lid = cg * 16 + rg;
        if (kc > 0) {
            float* r = hs0 + ((kc - 1) * 64 + lid) * 17;
#pragma unroll
            for (int c = 0; c < 2; c++)
#pragma unroll
                for (int m = 0; m < 4; m++) {
                    r[c * 4 + m]     = accI[c][m];
                    r[8 + c * 4 + m] = accF[c][m];
                }
        }
        __syncthreads();

        const size_t ob = (size_t)t * (BATCH * DH);
        if (kc == 0) {
#pragma unroll
            for (int rk = 0; rk < 3; rk++) {
                const float* r = hs0 + (rk * 64 + lid) * 17;
#pragma unroll
                for (int c = 0; c < 2; c++)
#pragma unroll
                    for (int m = 0; m < 4; m++) {
                        accI[c][m] += r[c * 4 + m];
                        accF[c][m] += r[8 + c * 4 + m];
                    }
            }
#pragma unroll
            for (int m = 0; m < 4; m++) {
                const int row = rg + 16 * m;
                const size_t base = ob + (size_t)row * DH + colg;
#pragma unroll
                for (int c = 0; c < 2; c++) {
                    const float bi = c ? biB : biA;
                    const float bf = c ? bfB : bfA;
                    const float pi = accI[c][m] + bi + g_ix[base + c];
                    const float pv = accF[c][m] + bf + g_fx[base + c];
                    const float ig = 1.f / (1.f + expf(-pi));
                    const float fg = 1.f / (1.f + expf(-pv));
                    const float hp = hprev[(size_t)row * DH + colg + c];
                    const float cc = ig * g_ct[base + c] + fg * hp;
                    const float hn = tanhf(cc);
                    out[base + c] = hn;
                    if (t == T_STEPS - 1) {
                        const size_t tb = (size_t)T_STEPS * BATCH * DH;
                        out[tb + (size_t)row * DH + colg + c] = hn;
                    }
                }
            }
        }

        // ---- grid-wide barrier (monotonic counter; host resets per launch) ----
        __threadfence();
        __syncthreads();
        if (tid == 0) {
            atomicAdd(&g_bar, 1u);
            const unsigned target = (unsigned)(t + 1) * nb;
            while (*((volatile unsigned*)&g_bar) < target) { }
            __threadfence();
        }
        __syncthreads();

        hprev = out + ob;
    }
}

// ---------------------------------------------------------------------------
extern "C" void kernel_launch(void* const* d_in, const int* in_sizes, int n_in,
                              void* d_out, int out_size)
{
    const float* x    = (const float*)d_in[0];
    const float* h0   = (const float*)d_in[1];
    const float* w_cx = (const float*)d_in[2];
    const float* w_ic = (const float*)d_in[3];
    const float* w_ix = (const float*)d_in[4];
    const float* w_fc = (const float*)d_in[5];
    const float* w_fx = (const float*)d_in[6];
    const float* b_cx = (const float*)d_in[7];
    const float* b_ic = (const float*)d_in[8];
    const float* b_ix = (const float*)d_in[9];
    const float* b_fc = (const float*)d_in[10];
    const float* b_fx = (const float*)d_in[11];
    float* out = (float*)d_out;

    // reset grid-barrier counter (graph-capturable async memset)
    void* barAddr = nullptr;
    cudaGetSymbolAddress(&barAddr, g_bar);
    cudaMemsetAsync(barAddr, 0, sizeof(unsigned), 0);

    // 1) input projections
    dim3 pgrid(DH / 64, (T_STEPS * BATCH) / 64);   // (16, 512)
    proj_kernel<<<pgrid, 256>>>(x, w_cx, w_ix, w_fx, b_cx, b_ix, b_fx);

    // 2) persistent recurrence
    cudaFuncSetAttribute(recur_kernel,
                         cudaFuncAttributeMaxDynamicSharedMemorySize, RSMEM);
    recur_kernel<<<RBLOCKS, 256, RSMEM>>>(h0, w_ic, w_fc, b_ic, b_fc, out);
}

// round 7
// speedup vs baseline: 1.7313x; 1.3180x over previous
#include <cuda_runtime.h>
#include <math.h>

#define T_STEPS 512
#define BATCH   64
#define DH      1024
#define DIN     1024

// Scratch: precomputed input projections (ctilde, ix, fx), each [T,B,H] f32.
__device__ float g_ct[(size_t)T_STEPS * BATCH * DH];
__device__ float g_ix[(size_t)T_STEPS * BATCH * DH];
__device__ float g_fx[(size_t)T_STEPS * BATCH * DH];
__device__ unsigned g_bar;

// ---------------------------------------------------------------------------
// Kernel 1: fused input projections (measured ~FMA-bound at fp32; ~88% of
// the fp32 FFMA floor — unchanged this round).
// ---------------------------------------------------------------------------
__global__ void __launch_bounds__(256) proj_kernel(
    const float* __restrict__ x,
    const float* __restrict__ w_cx, const float* __restrict__ w_ix,
    const float* __restrict__ w_fx,
    const float* __restrict__ b_cx, const float* __restrict__ b_ix,
    const float* __restrict__ b_fx)
{
    __shared__ float As[16][64];      // [k][row]
    __shared__ float Ws[3][16][64];   // [m][k][col]

    const int tid = threadIdx.x;
    const int tx  = tid & 15;
    const int ty  = tid >> 4;
    const int rowBase = blockIdx.y * 64;
    const int colBase = blockIdx.x * 64;

    const int lrow = tid >> 2;
    const int lk   = (tid & 3) * 4;

    const float* xp  = x    + (size_t)(rowBase + lrow) * DIN + lk;
    const float* wp0 = w_cx + (size_t)(colBase + lrow) * DIN + lk;
    const float* wp1 = w_ix + (size_t)(colBase + lrow) * DIN + lk;
    const float* wp2 = w_fx + (size_t)(colBase + lrow) * DIN + lk;

    float acc[3][4][4];
#pragma unroll
    for (int m = 0; m < 3; m++)
#pragma unroll
        for (int i = 0; i < 4; i++)
#pragma unroll
            for (int jj = 0; jj < 4; jj++) acc[m][i][jj] = 0.f;

    float4 ga = *(const float4*)(xp);
    float4 g0 = *(const float4*)(wp0);
    float4 g1 = *(const float4*)(wp1);
    float4 g2 = *(const float4*)(wp2);

    for (int kk = 0; kk < DIN; kk += 16) {
        __syncthreads();
        As[lk + 0][lrow] = ga.x; As[lk + 1][lrow] = ga.y;
        As[lk + 2][lrow] = ga.z; As[lk + 3][lrow] = ga.w;
        Ws[0][lk + 0][lrow] = g0.x; Ws[0][lk + 1][lrow] = g0.y;
        Ws[0][lk + 2][lrow] = g0.z; Ws[0][lk + 3][lrow] = g0.w;
        Ws[1][lk + 0][lrow] = g1.x; Ws[1][lk + 1][lrow] = g1.y;
        Ws[1][lk + 2][lrow] = g1.z; Ws[1][lk + 3][lrow] = g1.w;
        Ws[2][lk + 0][lrow] = g2.x; Ws[2][lk + 1][lrow] = g2.y;
        Ws[2][lk + 2][lrow] = g2.z; Ws[2][lk + 3][lrow] = g2.w;
        __syncthreads();

        if (kk + 16 < DIN) {
            ga = *(const float4*)(xp  + kk + 16);
            g0 = *(const float4*)(wp0 + kk + 16);
            g1 = *(const float4*)(wp1 + kk + 16);
            g2 = *(const float4*)(wp2 + kk + 16);
        }

#pragma unroll
        for (int k = 0; k < 16; k++) {
            const float4 a4 = *(const float4*)&As[k][ty * 4];
            const float4 b0 = *(const float4*)&Ws[0][k][tx * 4];
            const float4 b1 = *(const float4*)&Ws[1][k][tx * 4];
            const float4 b2 = *(const float4*)&Ws[2][k][tx * 4];
            const float av[4] = {a4.x, a4.y, a4.z, a4.w};
            const float bv[3][4] = {{b0.x, b0.y, b0.z, b0.w},
                                    {b1.x, b1.y, b1.z, b1.w},
                                    {b2.x, b2.y, b2.z, b2.w}};
#pragma unroll
            for (int m = 0; m < 3; m++)
#pragma unroll
                for (int i = 0; i < 4; i++)
#pragma unroll
                    for (int jj = 0; jj < 4; jj++)
                        acc[m][i][jj] += av[i] * bv[m][jj];
        }
    }

    const float4 bb0 = *(const float4*)(b_cx + colBase + tx * 4);
    const float4 bb1 = *(const float4*)(b_ix + colBase + tx * 4);
    const float4 bb2 = *(const float4*)(b_fx + colBase + tx * 4);
#pragma unroll
    for (int i = 0; i < 4; i++) {
        const size_t off = (size_t)(rowBase + ty * 4 + i) * DH + colBase + tx * 4;
        float4 o;
        o.x = acc[0][i][0] + bb0.x; o.y = acc[0][i][1] + bb0.y;
        o.z = acc[0][i][2] + bb0.z; o.w = acc[0][i][3] + bb0.w;
        *(float4*)(g_ct + off) = o;
        o.x = acc[1][i][0] + bb1.x; o.y = acc[1][i][1] + bb1.y;
        o.z = acc[1][i][2] + bb1.z; o.w = acc[1][i][3] + bb1.w;
        *(float4*)(g_ix + off) = o;
        o.x = acc[2][i][0] + bb2.x; o.y = acc[2][i][1] + bb2.y;
        o.z = acc[2][i][2] + bb2.z; o.w = acc[2][i][3] + bb2.w;
        *(float4*)(g_fx + off) = o;
    }
}

// ---------------------------------------------------------------------------
// Kernel 2: persistent recurrence v4 — occupancy fix.
//
// 128 blocks x 512 threads (16 warps/SM = 4 per SMSP; R6 had only 2/SMSP and
// measured ~2.3x the FMA floor -> latency-bound). Block owns 8 h-columns.
//   kc = tid>>6 (0..7): 8-way k split, 8 k per stage per thread
//   cg = (tid>>4)&3:    col pair (2 cols)
//   rg = tid&15:        rows rg, rg+16, rg+32, rg+48
// 16 fp32 accumulators/thread (2 col x 4 row x 2 gate). Stages of 64 k,
// double-buffered [64][68] tile (conflict-free LDS.128; w reads broadcast).
// Per SM per step: 1M FMA -> 16.4K cyc FFMA-pipe floor; crossbar ~2.5K cyc.
// Epilogue DRAM operands (g_ix/g_fx/g_ct + hprev diag) prefetched at step
// start so their latency hides under the 16-stage mainloop.
// ---------------------------------------------------------------------------
#define RBLOCKS   128
#define RTHREADS  512
#define HS_STRIDE 68
#define HS_TILE   (64 * HS_STRIDE)                     // 4352 floats / buffer
#define RSMEM     ((16 * DH + 2 * HS_TILE) * 4)        // ~98 KB

__global__ void __launch_bounds__(RTHREADS) recur_kernel(
    const float* __restrict__ h0,
    const float* __restrict__ w_ic, const float* __restrict__ w_fc,
    const float* __restrict__ b_ic, const float* __restrict__ b_fc,
    float* __restrict__ out)
{
    extern __shared__ float sm[];
    float* wi_s = sm;                 // [8][1024]
    float* wf_s = sm + 8 * DH;        // [8][1024]
    float* hs0  = sm + 16 * DH;       // h tile buffer 0 (also reduction scratch)
    float* hs1  = hs0 + HS_TILE;      // h tile buffer 1

    const int tid = threadIdx.x;
    const int kc  = tid >> 6;         // 0..7
    const int cg  = (tid >> 4) & 3;   // 0..3
    const int rg  = tid & 15;         // 0..15
    const int jb  = blockIdx.x;
    const int c0  = cg * 2;
    const int colg = jb * 8 + c0;
    const int lid  = cg * 16 + rg;    // 0..63

    // preload weight slices (8 rows x 1024, both gates)
    {
        const float4* gi = (const float4*)(w_ic + (size_t)jb * 8 * DH);
        const float4* gf = (const float4*)(w_fc + (size_t)jb * 8 * DH);
        float4* si = (float4*)wi_s;
        float4* sf = (float4*)wf_s;
        for (int i = tid; i < 8 * DH / 4; i += RTHREADS) { si[i] = gi[i]; sf[i] = gf[i]; }
    }
    const float* wiA = wi_s + (size_t)c0 * DH;
    const float* wiB = wi_s + (size_t)(c0 + 1) * DH;
    const float* wfA = wf_s + (size_t)c0 * DH;
    const float* wfB = wf_s + (size_t)(c0 + 1) * DH;
    const float biA = b_ic[colg], biB = b_ic[colg + 1];
    const float bfA = b_fc[colg], bfB = b_fc[colg + 1];
    __syncthreads();

    const unsigned nb = gridDim.x;
    const float* hprev = h0;

    // fill mapping: 2 float4 per thread per stage
    const int frow0 = tid >> 4;            // 0..31  (u=0)
    const int frow1 = (tid + RTHREADS) >> 4;  // 32..63 (u=1)
    const int fq    = (tid & 15) * 4;      // k offset within 64-k stage
    // compute-read base: hs[(rg + 16m)*68 + kc*8 + ...]
    const int rdoff = rg * HS_STRIDE + kc * 8;

    for (int t = 0; t < T_STEPS; t++) {
        float accI[2][4], accF[2][4];
#pragma unroll
        for (int c = 0; c < 2; c++)
#pragma unroll
            for (int m = 0; m < 4; m++) { accI[c][m] = 0.f; accF[c][m] = 0.f; }

        const size_t ob = (size_t)t * (BATCH * DH);

        // ---- prefetch epilogue operands (kc==0 threads; hides DRAM lat) ----
        float2 e_ix[4], e_fx[4], e_ct[4], e_hp[4];
        if (kc == 0) {
#pragma unroll
            for (int m = 0; m < 4; m++) {
                const int row = rg + 16 * m;
                const size_t base = ob + (size_t)row * DH + colg;
                e_ix[m] = *(const float2*)(g_ix + base);
                e_fx[m] = *(const float2*)(g_fx + base);
                e_ct[m] = *(const float2*)(g_ct + base);
                e_hp[m] = *(const float2*)(hprev + (size_t)row * DH + colg);
            }
        }

        // ---- stage 0 fill ----
        float4 pf0 = *(const float4*)(hprev + (size_t)frow0 * DH + fq);
        float4 pf1 = *(const float4*)(hprev + (size_t)frow1 * DH + fq);
        *(float4*)(hs0 + frow0 * HS_STRIDE + fq) = pf0;
        *(float4*)(hs1 - HS_TILE + frow1 * HS_STRIDE + fq) = pf1;  // == hs0 region
        __syncthreads();

#pragma unroll 1
        for (int s = 0; s < 16; s++) {
            const float* cur = (s & 1) ? hs1 : hs0;
            float* nxt = (s & 1) ? hs0 : hs1;

            if (s < 15) {   // issue next-stage global loads first (overlap)
                pf0 = *(const float4*)(hprev + (size_t)frow0 * DH + (s + 1) * 64 + fq);
                pf1 = *(const float4*)(hprev + (size_t)frow1 * DH + (s + 1) * 64 + fq);
            }

            const int kb = s * 64 + kc * 8;
            const float* cb = cur + rdoff;
#pragma unroll
            for (int j4 = 0; j4 < 2; j4++) {
                const float4 h0v = *(const float4*)(cb + j4 * 4 + 0 * 16 * HS_STRIDE);
                const float4 h1v = *(const float4*)(cb + j4 * 4 + 1 * 16 * HS_STRIDE);
                const float4 h2v = *(const float4*)(cb + j4 * 4 + 2 * 16 * HS_STRIDE);
                const float4 h3v = *(const float4*)(cb + j4 * 4 + 3 * 16 * HS_STRIDE);
                const float4 wiAv = *(const float4*)(wiA + kb + j4 * 4);
                const float4 wiBv = *(const float4*)(wiB + kb + j4 * 4);
                const float4 wfAv = *(const float4*)(wfA + kb + j4 * 4);
                const float4 wfBv = *(const float4*)(wfB + kb + j4 * 4);
                const float hm[4][4] = {{h0v.x, h0v.y, h0v.z, h0v.w},
                                        {h1v.x, h1v.y, h1v.z, h1v.w},
                                        {h2v.x, h2v.y, h2v.z, h2v.w},
                                        {h3v.x, h3v.y, h3v.z, h3v.w}};
                const float wa[4] = {wiAv.x, wiAv.y, wiAv.z, wiAv.w};
                const float wb[4] = {wiBv.x, wiBv.y, wiBv.z, wiBv.w};
                const float wc[4] = {wfAv.x, wfAv.y, wfAv.z, wfAv.w};
                const float wd[4] = {wfBv.x, wfBv.y, wfBv.z, wfBv.w};
#pragma unroll
                for (int j = 0; j < 4; j++)
#pragma unroll
                    for (int m = 0; m < 4; m++) {
                        accI[0][m] += hm[m][j] * wa[j];
                        accI[1][m] += hm[m][j] * wb[j];
                        accF[0][m] += hm[m][j] * wc[j];
                        accF[1][m] += hm[m][j] * wd[j];
                    }
            }

            if (s < 15) {
                *(float4*)(nxt + frow0 * HS_STRIDE + fq) = pf0;
                *(float4*)(nxt + (frow1 - 32 + 32) * HS_STRIDE + fq) = pf1;
                __syncthreads();
            }
        }

        // ---- 8-way kc reduction through smem (stride-17 pad) ----
        __syncthreads();           // all compute done; hs0/hs1 reusable
        if (kc > 0) {
            float* r = hs0 + ((kc - 1) * 64 + lid) * 17;
#pragma unroll
            for (int c = 0; c < 2; c++)
#pragma unroll
                for (int m = 0; m < 4; m++) {
                    r[c * 4 + m]     = accI[c][m];
                    r[8 + c * 4 + m] = accF[c][m];
                }
        }
        __syncthreads();

        if (kc == 0) {
#pragma unroll
            for (int rk = 0; rk < 7; rk++) {
                const float* r = hs0 + (rk * 64 + lid) * 17;
#pragma unroll
                for (int c = 0; c < 2; c++)
#pragma unroll
                    for (int m = 0; m < 4; m++) {
                        accI[c][m] += r[c * 4 + m];
                        accF[c][m] += r[8 + c * 4 + m];
                    }
            }
            // gates + cell update + output (prefetched operands)
#pragma unroll
            for (int m = 0; m < 4; m++) {
                const int row = rg + 16 * m;
                const size_t base = ob + (size_t)row * DH + colg;
                const float pix[2] = {e_ix[m].x, e_ix[m].y};
                const float pfx[2] = {e_fx[m].x, e_fx[m].y};
                const float pct[2] = {e_ct[m].x, e_ct[m].y};
                const float php[2] = {e_hp[m].x, e_hp[m].y};
#pragma unroll
                for (int c = 0; c < 2; c++) {
                    const float bi = c ? biB : biA;
                    const float bf = c ? bfB : bfA;
                    const float pi = accI[c][m] + bi + pix[c];
                    const float pv = accF[c][m] + bf + pfx[c];
                    const float ig = 1.f / (1.f + expf(-pi));
                    const float fg = 1.f / (1.f + expf(-pv));
                    const float cc = ig * pct[c] + fg * php[c];
                    const float hn = tanhf(cc);
                    out[base + c] = hn;
                    if (t == T_STEPS - 1) {
                        const size_t tb = (size_t)T_STEPS * BATCH * DH;
                        out[tb + (size_t)row * DH + colg + c] = hn;
                    }
                }
            }
        }

        // ---- grid-wide barrier (monotonic counter; host resets per launch) ----
        __threadfence();
        __syncthreads();
        if (tid == 0) {
            atomicAdd(&g_bar, 1u);
            const unsigned target = (unsigned)(t + 1) * nb;
            while (*((volatile unsigned*)&g_bar) < target) { }
            __threadfence();   // acquire: CCTL.IVALL flushes stale L1 for the SM
        }
        __syncthreads();

        hprev = out + ob;
    }
}

// ---------------------------------------------------------------------------
extern "C" void kernel_launch(void* const* d_in, const int* in_sizes, int n_in,
                              void* d_out, int out_size)
{
    const float* x    = (const float*)d_in[0];
    const float* h0   = (const float*)d_in[1];
    const float* w_cx = (const float*)d_in[2];
    const float* w_ic = (const float*)d_in[3];
    const float* w_ix = (const float*)d_in[4];
    const float* w_fc = (const float*)d_in[5];
    const float* w_fx = (const float*)d_in[6];
    const float* b_cx = (const float*)d_in[7];
    const float* b_ic = (const float*)d_in[8];
    const float* b_ix = (const float*)d_in[9];
    const float* b_fc = (const float*)d_in[10];
    const float* b_fx = (const float*)d_in[11];
    float* out = (float*)d_out;

    // reset grid-barrier counter (graph-capturable async memset)
    void* barAddr = nullptr;
    cudaGetSymbolAddress(&barAddr, g_bar);
    cudaMemsetAsync(barAddr, 0, sizeof(unsigned), 0);

    // 1) input projections
    dim3 pgrid(DH / 64, (T_STEPS * BATCH) / 64);   // (16, 512)
    proj_kernel<<<pgrid, 256>>>(x, w_cx, w_ix, w_fx, b_cx, b_ix, b_fx);

    // 2) persistent recurrence
    cudaFuncSetAttribute(recur_kernel,
                         cudaFuncAttributeMaxDynamicSharedMemorySize, RSMEM);
    recur_kernel<<<RBLOCKS, RTHREADS, RSMEM>>>(h0, w_ic, w_fc, b_ic, b_fc, out);
}

// round 10
// speedup vs baseline: 2.1409x; 1.2366x over previous
#include <cuda_runtime.h>
#include <cuda_bf16.h>
#include <math.h>
#include <stdint.h>

#define T_STEPS 512
#define BATCH   64
#define DH      1024
#define DIN     1024
#define NROWS   (T_STEPS * BATCH)        // 32768

// Scratch: precomputed input projections (ctilde, ix, fx), each [T,B,H] f32.
__device__ float g_ct[(size_t)NROWS * DH];
__device__ float g_ix[(size_t)NROWS * DH];
__device__ float g_fx[(size_t)NROWS * DH];
__device__ unsigned g_bar;

// bf16 split scratch: x (hi/lo) and concatenated weights [w_cx;w_ix;w_fx] (hi/lo)
__device__ __nv_bfloat16 g_xh[(size_t)NROWS * DIN];
__device__ __nv_bfloat16 g_xl[(size_t)NROWS * DIN];
__device__ __nv_bfloat16 g_wh[(size_t)3 * DH * DIN];
__device__ __nv_bfloat16 g_wl[(size_t)3 * DH * DIN];

// ---------------------------------------------------------------------------
// Split kernel: fp32 -> (hi, lo) bf16 pair.  a = hi + lo + O(2^-16 |a|)
// ---------------------------------------------------------------------------
__global__ void __launch_bounds__(256) split_kernel(
    const float* __restrict__ src,
    __nv_bfloat16* __restrict__ hi, __nv_bfloat16* __restrict__ lo, int n4)
{
    for (int i = blockIdx.x * blockDim.x + threadIdx.x; i < n4;
         i += gridDim.x * blockDim.x) {
        const float4 v = ((const float4*)src)[i];
        const __nv_bfloat16 h0 = __float2bfloat16(v.x);
        const __nv_bfloat16 h1 = __float2bfloat16(v.y);
        const __nv_bfloat16 h2 = __float2bfloat16(v.z);
        const __nv_bfloat16 h3 = __float2bfloat16(v.w);
        const __nv_bfloat16 l0 = __float2bfloat16(v.x - __bfloat162float(h0));
        const __nv_bfloat16 l1 = __float2bfloat16(v.y - __bfloat162float(h1));
        const __nv_bfloat16 l2 = __float2bfloat16(v.z - __bfloat162float(h2));
        const __nv_bfloat16 l3 = __float2bfloat16(v.w - __bfloat162float(h3));
        __nv_bfloat162* H = (__nv_bfloat162*)hi;
        __nv_bfloat162* L = (__nv_bfloat162*)lo;
        H[2 * i]     = __halves2bfloat162(h0, h1);
        H[2 * i + 1] = __halves2bfloat162(h2, h3);
        L[2 * i]     = __halves2bfloat162(l0, l1);
        L[2 * i + 1] = __halves2bfloat162(l2, l3);
    }
}

// ---------------------------------------------------------------------------
// Tensor-core projection GEMM: C[m][n] = sum_k x[m][k] * Wcat[n][k]  (+bias)
// split-3 bf16: Ah*Bh + Ah*Bl + Al*Bh, fp32 accumulate.
// Tile 128x64x32, 256 threads (8 warps: 4 along M x 2 along N), warp tile
// 32x32 = 2 m16 x 4 n8 mma tiles. smem rows stride 40 bf16 -> conflict-free
// 32-bit fragment loads (bank = 20*g + tg mod 32, all-distinct).
// ---------------------------------------------------------------------------
#define GSTR   40
#define SA_BUF (128 * GSTR)          // 5120 bf16 per A buffer
#define SB_BUF (64 * GSTR)           // 2560 bf16 per B buffer
#define GSMEM  ((2 * SA_BUF * 2 + 2 * SB_BUF * 2) * 2)   // bytes = 61440

__device__ __forceinline__ void mma_bf16(
    float& c0, float& c1, float& c2, float& c3,
    uint32_t a0, uint32_t a1, uint32_t a2, uint32_t a3,
    uint32_t b0, uint32_t b1)
{
    asm volatile(
        "mma.sync.aligned.m16n8k16.row.col.f32.bf16.bf16.f32 "
        "{%0,%1,%2,%3}, {%4,%5,%6,%7}, {%8,%9}, {%0,%1,%2,%3};"
        : "+f"(c0), "+f"(c1), "+f"(c2), "+f"(c3)
        : "r"(a0), "r"(a1), "r"(a2), "r"(a3), "r"(b0), "r"(b1));
}

__global__ void __launch_bounds__(256, 2) gemm_kernel(
    const float* __restrict__ b_cx, const float* __restrict__ b_ix,
    const float* __restrict__ b_fx)
{
    extern __shared__ __nv_bfloat16 gsm[];
    __nv_bfloat16* sAh = gsm;                              // [2][SA_BUF]
    __nv_bfloat16* sAl = gsm + 2 * SA_BUF;                 // [2][SA_BUF]
    __nv_bfloat16* sBh = gsm + 4 * SA_BUF;                 // [2][SB_BUF]
    __nv_bfloat16* sBl = gsm + 4 * SA_BUF + 2 * SB_BUF;    // [2][SB_BUF]

    const int tid   = threadIdx.x;
    const int lane  = tid & 31;
    const int warp  = tid >> 5;
    const int warpM = warp & 3;        // 0..3 -> m offset 32*warpM
    const int warpN = warp >> 2;       // 0..1 -> n offset 32*warpN
    const int g     = lane >> 2;       // 0..7
    const int tg    = lane & 3;        // 0..3

    const int mBase = blockIdx.y * 128;
    const int nGlob = blockIdx.x * 64;
    const int mat   = nGlob >> 10;     // 0..2
    const int nMat  = nGlob & 1023;

    // gmem staging mapping: thread loads 16B (8 bf16) chunks
    const int lr = tid >> 2;           // 0..63
    const int lc = (tid & 3) * 8;      // 0,8,16,24
    const size_t aOff0 = (size_t)(mBase + lr) * DIN + lc;
    const size_t aOff1 = (size_t)(mBase + 64 + lr) * DIN + lc;
    const size_t bOff  = (size_t)(nGlob + lr) * DIN + lc;

    float acc[2][4][4];
#pragma unroll
    for (int mt = 0; mt < 2; mt++)
#pragma unroll
        for (int nt = 0; nt < 4; nt++)
#pragma unroll
            for (int q = 0; q < 4; q++) acc[mt][nt][q] = 0.f;

    // prologue: stage 0
    uint4 rah0 = *(const uint4*)(g_xh + aOff0);
    uint4 rah1 = *(const uint4*)(g_xh + aOff1);
    uint4 ral0 = *(const uint4*)(g_xl + aOff0);
    uint4 ral1 = *(const uint4*)(g_xl + aOff1);
    uint4 rbh  = *(const uint4*)(g_wh + bOff);
    uint4 rbl  = *(const uint4*)(g_wl + bOff);
    {
        const int sa = lr * GSTR + lc;
        *(uint4*)(sAh + sa) = rah0;
        *(uint4*)(sAh + sa + 64 * GSTR) = rah1;
        *(uint4*)(sAl + sa) = ral0;
        *(uint4*)(sAl + sa + 64 * GSTR) = ral1;
        *(uint4*)(sBh + sa) = rbh;
        *(uint4*)(sBl + sa) = rbl;
    }
    __syncthreads();

    const int aRowOff0 = (warpM * 32 + g) * GSTR;       // + mt*16*GSTR (+8*GSTR)
    const int bColOff  = (warpN * 32 + g) * GSTR;       // + nt*8*GSTR

#pragma unroll 1
    for (int s = 0; s < 32; s++) {
        const int cur = s & 1;
        const __nv_bfloat16* Ah = sAh + cur * SA_BUF;
        const __nv_bfloat16* Al = sAl + cur * SA_BUF;
        const __nv_bfloat16* Bh = sBh + cur * SB_BUF;
        const __nv_bfloat16* Bl = sBl + cur * SB_BUF;

        if (s < 31) {   // prefetch next stage
            const int k0 = (s + 1) * 32;
            rah0 = *(const uint4*)(g_xh + aOff0 + k0);
            rah1 = *(const uint4*)(g_xh + aOff1 + k0);
            ral0 = *(const uint4*)(g_xl + aOff0 + k0);
            ral1 = *(const uint4*)(g_xl + aOff1 + k0);
            rbh  = *(const uint4*)(g_wh + bOff + k0);
            rbl  = *(const uint4*)(g_wl + bOff + k0);
        }

#pragma unroll
        for (int kk = 0; kk < 32; kk += 16) {
            uint32_t fah[2][4], fal[2][4], fbh[4][2], fbl[4][2];
#pragma unroll
            for (int mt = 0; mt < 2; mt++) {
                const int r = aRowOff0 + mt * 16 * GSTR + kk + tg * 2;
                fah[mt][0] = *(const uint32_t*)(Ah + r);
                fah[mt][1] = *(const uint32_t*)(Ah + r + 8 * GSTR);
                fah[mt][2] = *(const uint32_t*)(Ah + r + 8);
                fah[mt][3] = *(const uint32_t*)(Ah + r + 8 * GSTR + 8);
                fal[mt][0] = *(const uint32_t*)(Al + r);
                fal[mt][1] = *(const uint32_t*)(Al + r + 8 * GSTR);
                fal[mt][2] = *(const uint32_t*)(Al + r + 8);
                fal[mt][3] = *(const uint32_t*)(Al + r + 8 * GSTR + 8);
            }
#pragma unroll
            for (int nt = 0; nt < 4; nt++) {
                const int c = bColOff + nt * 8 * GSTR + kk + tg * 2;
                fbh[nt][0] = *(const uint32_t*)(Bh + c);
                fbh[nt][1] = *(const uint32_t*)(Bh + c + 8);
                fbl[nt][0] = *(const uint32_t*)(Bl + c);
                fbl[nt][1] = *(const uint32_t*)(Bl + c + 8);
            }
#pragma unroll
            for (int mt = 0; mt < 2; mt++)
#pragma unroll
                for (int nt = 0; nt < 4; nt++) {
                    mma_bf16(acc[mt][nt][0], acc[mt][nt][1],
                             acc[mt][nt][2], acc[mt][nt][3],
                             fah[mt][0], fah[mt][1], fah[mt][2], fah[mt][3],
                             fbh[nt][0], fbh[nt][1]);
                    mma_bf16(acc[mt][nt][0], acc[mt][nt][1],
                             acc[mt][nt][2], acc[mt][nt][3],
                             fah[mt][0], fah[mt][1], fah[mt][2], fah[mt][3],
                             fbl[nt][0], fbl[nt][1]);
                    mma_bf16(acc[mt][nt][0], acc[mt][nt][1],
                             acc[mt][nt][2], acc[mt][nt][3],
                             fal[mt][0], fal[mt][1], fal[mt][2], fal[mt][3],
                             fbh[nt][0], fbh[nt][1]);
                }
        }

        if (s < 31) {   // store next stage, one sync per stage
            const int nxt = cur ^ 1;
            const int sa = lr * GSTR + lc;
            *(uint4*)(sAh + nxt * SA_BUF + sa) = rah0;
            *(uint4*)(sAh + nxt * SA_BUF + sa + 64 * GSTR) = rah1;
            *(uint4*)(sAl + nxt * SA_BUF + sa) = ral0;
            *(uint4*)(sAl + nxt * SA_BUF + sa + 64 * GSTR) = ral1;
            *(uint4*)(sBh + nxt * SB_BUF + sa) = rbh;
            *(uint4*)(sBl + nxt * SB_BUF + sa) = rbl;
            __syncthreads();
        }
    }

    // epilogue: add bias, write fp32
    float* dst = (mat == 0) ? g_ct : ((mat == 1) ? g_ix : g_fx);
    const float* bias = (mat == 0) ? b_cx : ((mat == 1) ? b_ix : b_fx);
#pragma unroll
    for (int mt = 0; mt < 2; mt++)
#pragma unroll
        for (int nt = 0; nt < 4; nt++) {
            const int col = nMat + warpN * 32 + nt * 8 + tg * 2;
            const float2 bb = *(const float2*)(bias + col);
            const int r0 = mBase + warpM * 32 + mt * 16 + g;
            float2 o0 = {acc[mt][nt][0] + bb.x, acc[mt][nt][1] + bb.y};
            float2 o1 = {acc[mt][nt][2] + bb.x, acc[mt][nt][3] + bb.y};
            *(float2*)(dst + (size_t)r0 * DH + col) = o0;
            *(float2*)(dst + (size_t)(r0 + 8) * DH + col) = o1;
        }
}

// ---------------------------------------------------------------------------
// Persistent recurrence (unchanged from R7 — measured 11.3 us/step).
// ---------------------------------------------------------------------------
#define RBLOCKS   128
#define RTHREADS  512
#define HS_STRIDE 68
#define HS_TILE   (64 * HS_STRIDE)
#define RSMEM     ((16 * DH + 2 * HS_TILE) * 4)

__global__ void __launch_bounds__(RTHREADS) recur_kernel(
    const float* __restrict__ h0,
    const float* __restrict__ w_ic, const float* __restrict__ w_fc,
    const float* __restrict__ b_ic, const float* __restrict__ b_fc,
    float* __restrict__ out)
{
    extern __shared__ float sm[];
    float* wi_s = sm;
    float* wf_s = sm + 8 * DH;
    float* hs0  = sm + 16 * DH;
    float* hs1  = hs0 + HS_TILE;

    const int tid = threadIdx.x;
    const int kc  = tid >> 6;
    const int cg  = (tid >> 4) & 3;
    const int rg  = tid & 15;
    const int jb  = blockIdx.x;
    const int c0  = cg * 2;
    const int colg = jb * 8 + c0;
    const int lid  = cg * 16 + rg;

    {
        const float4* gi = (const float4*)(w_ic + (size_t)jb * 8 * DH);
        const float4* gf = (const float4*)(w_fc + (size_t)jb * 8 * DH);
        float4* si = (float4*)wi_s;
        float4* sf = (float4*)wf_s;
        for (int i = tid; i < 8 * DH / 4; i += RTHREADS) { si[i] = gi[i]; sf[i] = gf[i]; }
    }
    const float* wiA = wi_s + (size_t)c0 * DH;
    const float* wiB = wi_s + (size_t)(c0 + 1) * DH;
    const float* wfA = wf_s + (size_t)c0 * DH;
    const float* wfB = wf_s + (size_t)(c0 + 1) * DH;
    const float biA = b_ic[colg], biB = b_ic[colg + 1];
    const float bfA = b_fc[colg], bfB = b_fc[colg + 1];
    __syncthreads();

    const unsigned nb = gridDim.x;
    const float* hprev = h0;

    const int frow0 = tid >> 4;
    const int frow1 = (tid + RTHREADS) >> 4;
    const int fq    = (tid & 15) * 4;
    const int rdoff = rg * HS_STRIDE + kc * 8;

    for (int t = 0; t < T_STEPS; t++) {
        float accI[2][4], accF[2][4];
#pragma unroll
        for (int c = 0; c < 2; c++)
#pragma unroll
            for (int m = 0; m < 4; m++) { accI[c][m] = 0.f; accF[c][m] = 0.f; }

        const size_t ob = (size_t)t * (BATCH * DH);

        float2 e_ix[4], e_fx[4], e_ct[4], e_hp[4];
        if (kc == 0) {
#pragma unroll
            for (int m = 0; m < 4; m++) {
                const int row = rg + 16 * m;
                const size_t base = ob + (size_t)row * DH + colg;
                e_ix[m] = *(const float2*)(g_ix + base);
                e_fx[m] = *(const float2*)(g_fx + base);
                e_ct[m] = *(const float2*)(g_ct + base);
                e_hp[m] = *(const float2*)(hprev + (size_t)row * DH + colg);
            }
        }

        float4 pf0 = *(const float4*)(hprev + (size_t)frow0 * DH + fq);
        float4 pf1 = *(const float4*)(hprev + (size_t)frow1 * DH + fq);
        *(float4*)(hs0 + frow0 * HS_STRIDE + fq) = pf0;
        *(float4*)(hs0 + frow1 * HS_STRIDE + fq) = pf1;
        __syncthreads();

#pragma unroll 1
        for (int s = 0; s < 16; s++) {
            const float* cur = (s & 1) ? hs1 : hs0;
            float* nxt = (s & 1) ? hs0 : hs1;

            if (s < 15) {
                pf0 = *(const float4*)(hprev + (size_t)frow0 * DH + (s + 1) * 64 + fq);
                pf1 = *(const float4*)(hprev + (size_t)frow1 * DH + (s + 1) * 64 + fq);
            }

            const int kb = s * 64 + kc * 8;
            const float* cb = cur + rdoff;
#pragma unroll
            for (int j4 = 0; j4 < 2; j4++) {
                const float4 h0v = *(const float4*)(cb + j4 * 4 + 0 * 16 * HS_STRIDE);
                const float4 h1v = *(const float4*)(cb + j4 * 4 + 1 * 16 * HS_STRIDE);
                const float4 h2v = *(const float4*)(cb + j4 * 4 + 2 * 16 * HS_STRIDE);
                const float4 h3v = *(const float4*)(cb + j4 * 4 + 3 * 16 * HS_STRIDE);
                const float4 wiAv = *(const float4*)(wiA + kb + j4 * 4);
                const float4 wiBv = *(const float4*)(wiB + kb + j4 * 4);
                const float4 wfAv = *(const float4*)(wfA + kb + j4 * 4);
                const float4 wfBv = *(const float4*)(wfB + kb + j4 * 4);
                const float hm[4][4] = {{h0v.x, h0v.y, h0v.z, h0v.w},
                                        {h1v.x, h1v.y, h1v.z, h1v.w},
                                        {h2v.x, h2v.y, h2v.z, h2v.w},
                                        {h3v.x, h3v.y, h3v.z, h3v.w}};
                const float wa[4] = {wiAv.x, wiAv.y, wiAv.z, wiAv.w};
                const float wb[4] = {wiBv.x, wiBv.y, wiBv.z, wiBv.w};
                const float wc[4] = {wfAv.x, wfAv.y, wfAv.z, wfAv.w};
                const float wd[4] = {wfBv.x, wfBv.y, wfBv.z, wfBv.w};
#pragma unroll
                for (int j = 0; j < 4; j++)
#pragma unroll
                    for (int m = 0; m < 4; m++) {
                        accI[0][m] += hm[m][j] * wa[j];
                        accI[1][m] += hm[m][j] * wb[j];
                        accF[0][m] += hm[m][j] * wc[j];
                        accF[1][m] += hm[m][j] * wd[j];
                    }
            }

            if (s < 15) {
                *(float4*)(nxt + frow0 * HS_STRIDE + fq) = pf0;
                *(float4*)(nxt + frow1 * HS_STRIDE + fq) = pf1;
                __syncthreads();
            }
        }

        __syncthreads();
        if (kc > 0) {
            float* r = hs0 + ((kc - 1) * 64 + lid) * 17;
#pragma unroll
            for (int c = 0; c < 2; c++)
#pragma unroll
                for (int m = 0; m < 4; m++) {
                    r[c * 4 + m]     = accI[c][m];
                    r[8 + c * 4 + m] = accF[c][m];
                }
        }
        __syncthreads();

        if (kc == 0) {
#pragma unroll
            for (int rk = 0; rk < 7; rk++) {
                const float* r = hs0 + (rk * 64 + lid) * 17;
#pragma unroll
                for (int c = 0; c < 2; c++)
#pragma unroll
                    for (int m = 0; m < 4; m++) {
                        accI[c][m] += r[c * 4 + m];
                        accF[c][m] += r[8 + c * 4 + m];
                    }
            }
#pragma unroll
            for (int m = 0; m < 4; m++) {
                const int row = rg + 16 * m;
                const size_t base = ob + (size_t)row * DH + colg;
                const float pix[2] = {e_ix[m].x, e_ix[m].y};
                const float pfx[2] = {e_fx[m].x, e_fx[m].y};
                const float pct[2] = {e_ct[m].x, e_ct[m].y};
                const float php[2] = {e_hp[m].x, e_hp[m].y};
#pragma unroll
                for (int c = 0; c < 2; c++) {
                    const float bi = c ? biB : biA;
                    const float bf = c ? bfB : bfA;
                    const float pi = accI[c][m] + bi + pix[c];
                    const float pv = accF[c][m] + bf + pfx[c];
                    const float ig = 1.f / (1.f + expf(-pi));
                    const float fg = 1.f / (1.f + expf(-pv));
                    const float cc = ig * pct[c] + fg * php[c];
                    const float hn = tanhf(cc);
                    out[base + c] = hn;
                    if (t == T_STEPS - 1) {
                        const size_t tb = (size_t)T_STEPS * BATCH * DH;
                        out[tb + (size_t)row * DH + colg + c] = hn;
                    }
                }
            }
        }

        __threadfence();
        __syncthreads();
        if (tid == 0) {
            atomicAdd(&g_bar, 1u);
            const unsigned target = (unsigned)(t + 1) * nb;
            while (*((volatile unsigned*)&g_bar) < target) { }
            __threadfence();
        }
        __syncthreads();

        hprev = out + ob;
    }
}

// ---------------------------------------------------------------------------
extern "C" void kernel_launch(void* const* d_in, const int* in_sizes, int n_in,
                              void* d_out, int out_size)
{
    const float* x    = (const float*)d_in[0];
    const float* h0   = (const float*)d_in[1];
    const float* w_cx = (const float*)d_in[2];
    const float* w_ic = (const float*)d_in[3];
    const float* w_ix = (const float*)d_in[4];
    const float* w_fc = (const float*)d_in[5];
    const float* w_fx = (const float*)d_in[6];
    const float* b_cx = (const float*)d_in[7];
    const float* b_ic = (const float*)d_in[8];
    const float* b_ix = (const float*)d_in[9];
    const float* b_fc = (const float*)d_in[10];
    const float* b_fx = (const float*)d_in[11];
    float* out = (float*)d_out;

    // reset grid-barrier counter (graph-capturable async memset)
    void* barAddr = nullptr;
    cudaGetSymbolAddress(&barAddr, g_bar);
    cudaMemsetAsync(barAddr, 0, sizeof(unsigned), 0);

    // scratch symbol addresses
    void *xh, *xl, *wh, *wl;
    cudaGetSymbolAddress(&xh, g_xh);
    cudaGetSymbolAddress(&xl, g_xl);
    cudaGetSymbolAddress(&wh, g_wh);
    cudaGetSymbolAddress(&wl, g_wl);

    // 1) split x and weights into bf16 hi/lo
    split_kernel<<<2048, 256>>>(x, (__nv_bfloat16*)xh, (__nv_bfloat16*)xl,
                                (NROWS * DIN) / 4);
    const int wn4 = (DH * DIN) / 4;
    split_kernel<<<512, 256>>>(w_cx, (__nv_bfloat16*)wh, (__nv_bfloat16*)wl, wn4);
    split_kernel<<<512, 256>>>(w_ix, (__nv_bfloat16*)wh + (size_t)DH * DIN,
                               (__nv_bfloat16*)wl + (size_t)DH * DIN, wn4);
    split_kernel<<<512, 256>>>(w_fx, (__nv_bfloat16*)wh + (size_t)2 * DH * DIN,
                               (__nv_bfloat16*)wl + (size_t)2 * DH * DIN, wn4);

    // 2) tensor-core projection GEMM: [32768 x 1024] x [3072 x 1024]^T
    cudaFuncSetAttribute(gemm_kernel,
                         cudaFuncAttributeMaxDynamicSharedMemorySize, GSMEM);
    dim3 ggrid(3 * DH / 64, NROWS / 128);    // (48, 256), x fast for L2 reuse
    gemm_kernel<<<ggrid, 256, GSMEM>>>(b_cx, b_ix, b_fx);

    // 3) persistent recurrence
    cudaFuncSetAttribute(recur_kernel,
                         cudaFuncAttributeMaxDynamicSharedMemorySize, RSMEM);
    recur_kernel<<<RBLOCKS, RTHREADS, RSMEM>>>(h0, w_ic, w_fc, b_ic, b_fc, out);
}